// round 2
// baseline (speedup 1.0000x reference)
#include <cuda_runtime.h>
#include <stdint.h>

#define N_NODES 100000
#define DIM 256
#define NS 64
#define CANDN 160
#define TK 16
#define MODCAP 128

// -------- scratch (static device globals; no runtime allocation) --------
__device__ float g_D[(size_t)NS * N_NODES];   // D[s][j] = dot(x_s, V_j)  (25.6 MB)
__device__ float g_vn[N_NODES];               // ||V_j||^2
__device__ float g_G[NS * NS];                // G[i][t] = dot(x_i, x_t); diag = ||x||^2
__device__ unsigned long long g_cand[NS * CANDN]; // per sample: sorted (d2bits<<32)|idx

__device__ __forceinline__ unsigned long long u64min(unsigned long long a, unsigned long long b) { return a < b ? a : b; }
__device__ __forceinline__ unsigned long long u64max(unsigned long long a, unsigned long long b) { return a > b ? a : b; }

// ---------------- K1: Gram matrix G = X X^T ----------------
__global__ void k_gram(const float* __restrict__ X) {
    __shared__ float sx[DIM];
    __shared__ float red[256];
    int b = blockIdx.x, tid = threadIdx.x;
    sx[tid] = X[b * DIM + tid];
    __syncthreads();
    int j = tid & 63, q = tid >> 6;
    const float* xj = X + (size_t)j * DIM + q * 64;
    const float* xb = sx + q * 64;
    float p = 0.f;
#pragma unroll
    for (int k = 0; k < 64; ++k) p += xb[k] * xj[k];
    red[tid] = p;
    __syncthreads();
    if (tid < 64)
        g_G[b * NS + tid] = red[tid] + red[tid + 64] + red[tid + 128] + red[tid + 192];
}

// ---------------- K2: D = X V^T and vnorms (main cost) ----------------
// block: 64 nodes; threads 256 = 16 sample-groups x 16 node-groups; 4x4 register tile.
__global__ __launch_bounds__(256) void k_gemm(const float* __restrict__ X, const float* __restrict__ V) {
    __shared__ __align__(16) float sX[64][68];   // sX[k][s]
    __shared__ __align__(16) float sV[64][68];   // sV[k][j]
    int tid = threadIdx.x;
    int j0 = blockIdx.x * 64;
    int nvalid = N_NODES - j0; if (nvalid > 64) nvalid = 64;
    int sg = tid & 15, jg = tid >> 4;
    int r = tid >> 2, kq = tid & 3;
    bool vok = (r < nvalid);

    float acc[4][4];
#pragma unroll
    for (int a = 0; a < 4; ++a)
#pragma unroll
        for (int c = 0; c < 4; ++c) acc[a][c] = 0.f;
    float vnacc = 0.f;

    const float* Xp = X + (size_t)r * DIM + kq * 4;
    const float* Vp = V + (size_t)(vok ? (j0 + r) : 0) * DIM + kq * 4;

    for (int kc = 0; kc < DIM; kc += 64) {
#pragma unroll
        for (int u = 0; u < 4; ++u) {
            int k = kq * 4 + u * 16;
            float4 fx = *(const float4*)(Xp + kc + u * 16);
            sX[k + 0][r] = fx.x; sX[k + 1][r] = fx.y; sX[k + 2][r] = fx.z; sX[k + 3][r] = fx.w;
            float4 fv = vok ? *(const float4*)(Vp + kc + u * 16) : make_float4(0.f, 0.f, 0.f, 0.f);
            sV[k + 0][r] = fv.x; sV[k + 1][r] = fv.y; sV[k + 2][r] = fv.z; sV[k + 3][r] = fv.w;
            vnacc += fv.x * fv.x + fv.y * fv.y + fv.z * fv.z + fv.w * fv.w;
        }
        __syncthreads();
#pragma unroll 16
        for (int kk = 0; kk < 64; ++kk) {
            float4 xv = *(const float4*)&sX[kk][sg * 4];
            float4 vv = *(const float4*)&sV[kk][jg * 4];
            acc[0][0] += xv.x * vv.x; acc[0][1] += xv.x * vv.y; acc[0][2] += xv.x * vv.z; acc[0][3] += xv.x * vv.w;
            acc[1][0] += xv.y * vv.x; acc[1][1] += xv.y * vv.y; acc[1][2] += xv.y * vv.z; acc[1][3] += xv.y * vv.w;
            acc[2][0] += xv.z * vv.x; acc[2][1] += xv.z * vv.y; acc[2][2] += xv.z * vv.z; acc[2][3] += xv.z * vv.w;
            acc[3][0] += xv.w * vv.x; acc[3][1] += xv.w * vv.y; acc[3][2] += xv.w * vv.z; acc[3][3] += xv.w * vv.w;
        }
        __syncthreads();
    }

    // reduce vnorm across the 4 kq-threads of each row (adjacent lanes)
    vnacc += __shfl_down_sync(0xffffffffu, vnacc, 1);
    vnacc += __shfl_down_sync(0xffffffffu, vnacc, 2);
    if (kq == 0 && vok) g_vn[j0 + r] = vnacc;

    int jb = jg * 4;
    if (jb < nvalid) {
        bool full = (jb + 4 <= nvalid);
#pragma unroll
        for (int a = 0; a < 4; ++a) {
            int s = sg * 4 + a;
            float4 o = make_float4(acc[a][0], acc[a][1], acc[a][2], acc[a][3]);
            float* dst = g_D + (size_t)s * N_NODES + j0 + jb;
            if (full) {
                *(float4*)dst = o;
            } else {
                float ov[4] = {o.x, o.y, o.z, o.w};
                for (int c = 0; c < 4; ++c) if (jb + c < nvalid) dst[c] = ov[c];
            }
        }
    }
}

// ---------------- K3: per-sample top-CANDN baseline candidates ----------------
__global__ __launch_bounds__(256) void k_cand() {
    __shared__ unsigned long long keys[4096];
    int i = blockIdx.x, tid = threadIdx.x;
    float xn = g_G[i * NS + i];
    float lv[TK]; unsigned li[TK];
#pragma unroll
    for (int m = 0; m < TK; ++m) { lv[m] = 3.4e38f; li[m] = 0xffffffffu; }
    const float* Drow = g_D + (size_t)i * N_NODES;
    for (int j = tid; j < N_NODES; j += 256) {
        float d2 = xn - 2.f * __ldg(&Drow[j]) + __ldg(&g_vn[j]);
        if (d2 < lv[TK - 1]) {
            int pos = TK - 1;
            while (pos > 0 && lv[pos - 1] > d2) { lv[pos] = lv[pos - 1]; li[pos] = li[pos - 1]; --pos; }
            lv[pos] = d2; li[pos] = (unsigned)j;
        }
    }
#pragma unroll
    for (int m = 0; m < TK; ++m)
        keys[tid * TK + m] = ((unsigned long long)__float_as_uint(lv[m]) << 32) | li[m];
    __syncthreads();
    // bitonic sort ascending (d2, then idx)
    for (int k = 2; k <= 4096; k <<= 1) {
        for (int j2 = k >> 1; j2 > 0; j2 >>= 1) {
            for (int t = tid; t < 4096; t += 256) {
                int ixj = t ^ j2;
                if (ixj > t) {
                    unsigned long long a = keys[t], b = keys[ixj];
                    bool up = ((t & k) == 0);
                    if ((a > b) == up) { keys[t] = b; keys[ixj] = a; }
                }
            }
            __syncthreads();
        }
    }
    if (tid < CANDN) g_cand[i * CANDN + tid] = keys[tid];
}

// ---------------- K4: sequential 64-step BMU loop (single block) ----------------
__global__ __launch_bounds__(256) void k_seq(const int* __restrict__ itp, float* __restrict__ out) {
    __shared__ int   mod_idx[MODCAP];
    __shared__ float mod_vn[MODCAP];
    __shared__ float mod_D[MODCAP * 64];          // mod_D[m][t] = dot(x_t, V_node_m current)
    __shared__ unsigned bm[N_NODES / 32];         // modified-node bitmap (3125 words)
    __shared__ unsigned long long wred[16];
    __shared__ unsigned long long s_k1, s_k2;
    __shared__ int s_mb, s_ms, s_newb, s_news, s_nmod;

    int tid = threadIdx.x;
    for (int w = tid; w < N_NODES / 32; w += 256) bm[w] = 0;
    if (tid == 0) s_nmod = 0;
    int it = itp ? *itp : 0;
    float eb = 1.0f / (float)(it + 2);
    float en = 1.0f / (float)((it + 1) * 100);
    __syncthreads();

    unsigned long long kcur = (tid < CANDN) ? __ldg(&g_cand[tid]) : ~0ull;

    for (int i = 0; i < NS; ++i) {
        unsigned long long knext = (tid < CANDN && i + 1 < NS) ? __ldg(&g_cand[(i + 1) * CANDN + tid]) : ~0ull;
        float xn = g_G[i * NS + i];
        int nmod = s_nmod;

        unsigned long long k1 = ~0ull, k2 = ~0ull;
        if (tid < CANDN) {
            unsigned idx = (unsigned)kcur & 0xffffffffu;
            if (!((bm[idx >> 5] >> (idx & 31)) & 1u)) k1 = kcur;   // skip modified (covered below)
        }
        if (tid < nmod) {
            float d2 = xn - 2.f * mod_D[tid * 64 + i] + mod_vn[tid];
            unsigned long long key = ((unsigned long long)__float_as_uint(d2) << 32) | (unsigned)mod_idx[tid];
            if (key < k1) { k2 = k1; k1 = key; } else if (key < k2) k2 = key;
        }
        // warp-level top-2 reduction
#pragma unroll
        for (int off = 16; off; off >>= 1) {
            unsigned long long b1 = __shfl_down_sync(0xffffffffu, k1, off);
            unsigned long long b2 = __shfl_down_sync(0xffffffffu, k2, off);
            unsigned long long m1 = u64min(k1, b1);
            unsigned long long m2 = u64min(u64max(k1, b1), u64min(k2, b2));
            k1 = m1; k2 = m2;
        }
        if ((tid & 31) == 0) { wred[(tid >> 5) * 2] = k1; wred[(tid >> 5) * 2 + 1] = k2; }
        __syncthreads();
        if (tid == 0) {
            unsigned long long r1 = wred[0], r2 = wred[1];
            for (int w = 1; w < 8; ++w) {
                unsigned long long b1 = wred[w * 2], b2 = wred[w * 2 + 1];
                unsigned long long m1 = u64min(r1, b1);
                r2 = u64min(u64max(r1, b1), u64min(r2, b2));
                r1 = m1;
            }
            s_k1 = r1; s_k2 = r2;
            out[2 * i]     = sqrtf(__uint_as_float((unsigned)(r1 >> 32)) + 1e-12f);
            out[2 * i + 1] = sqrtf(__uint_as_float((unsigned)(r2 >> 32)) + 1e-12f);
            s_mb = -1; s_ms = -1;
        }
        __syncthreads();
        int nb  = (int)(s_k1 & 0xffffffffu);
        int nsd = (int)(s_k2 & 0xffffffffu);
        // locate in mod table (parallel)
        if (tid < nmod) {
            int mi = mod_idx[tid];
            if (mi == nb)  s_mb = tid;
            if (mi == nsd) s_ms = tid;
        }
        __syncthreads();
        if (tid == 0) {
            if (s_mb < 0) { s_mb = s_nmod++; mod_idx[s_mb] = nb;  bm[nb >> 5]  |= 1u << (nb & 31);  s_newb = 1; } else s_newb = 0;
            if (s_ms < 0) { s_ms = s_nmod++; mod_idx[s_ms] = nsd; bm[nsd >> 5] |= 1u << (nsd & 31); s_news = 1; } else s_news = 0;
        }
        __syncthreads();
        int mb = s_mb, ms = s_ms;
        // gather baseline rows for newly-touched nodes (parallel for b and s)
        if (s_newb) {
            if (tid < 64) mod_D[mb * 64 + tid] = g_D[(size_t)tid * N_NODES + nb];
            if (tid == 64) mod_vn[mb] = g_vn[nb];
        }
        if (s_news) {
            if (tid >= 128 && tid < 192) mod_D[ms * 64 + (tid - 128)] = g_D[(size_t)(tid - 128) * N_NODES + nsd];
            if (tid == 192) mod_vn[ms] = g_vn[nsd];
        }
        __syncthreads();
        // norm recurrences (must read OLD dot) ...
        if (tid == 0) {
            float dold = mod_D[mb * 64 + i];
            float om = 1.f - eb;
            mod_vn[mb] = om * om * mod_vn[mb] + 2.f * eb * om * dold + eb * eb * xn;
        }
        if (tid == 1) {
            float dold = mod_D[ms * 64 + i];
            float om = 1.f - en;
            mod_vn[ms] = om * om * mod_vn[ms] + 2.f * en * om * dold + en * en * xn;
        }
        __syncthreads();
        // ... then dot recurrences
        if (tid < 64) {
            mod_D[mb * 64 + tid] = (1.f - eb) * mod_D[mb * 64 + tid] + eb * g_G[i * NS + tid];
        } else if (tid < 128) {
            int t = tid - 64;
            mod_D[ms * 64 + t] = (1.f - en) * mod_D[ms * 64 + t] + en * g_G[i * NS + t];
        }
        __syncthreads();
        kcur = knext;
    }
}

extern "C" void kernel_launch(void* const* d_in, const int* in_sizes, int n_in,
                              void* d_out, int out_size) {
    const float* X = (const float*)d_in[0];       // data [64,256]
    const float* V = (const float*)d_in[1];       // V [100000,256]
    const int* itp = (n_in > 3) ? (const int*)d_in[3] : nullptr;  // it scalar
    float* out = (float*)d_out;                   // [64,2]

    k_gram<<<NS, 256>>>(X);
    k_gemm<<<(N_NODES + 63) / 64, 256>>>(X, V);
    k_cand<<<NS, 256>>>();
    k_seq<<<1, 256>>>(itp, out);
}

// round 3
// speedup vs baseline: 4.2269x; 4.2269x over previous
#include <cuda_runtime.h>
#include <stdint.h>

#define N_NODES 100000
#define DIM     256
#define NS      64
#define NPC     128                 // nodes per CTA in k_gemm
#define NSLICE  8                   // slices per sample in k_cand
#define SLICEN  (N_NODES / NSLICE)  // 12500
#define CANDN   160
#define TK      16
#define MODCAP  128
#define BMW     (N_NODES / 32)      // 3125

typedef unsigned long long u64;

// -------- scratch (static device globals; no runtime allocation) --------
__device__ float g_D[(size_t)NS * N_NODES];          // D[s][j] = dot(x_s, V_j)
__device__ float g_vn[N_NODES];                      // ||V_j||^2
__device__ float g_G[NS * NS];                       // Gram of X (diag = ||x||^2)
__device__ u64   g_scand[(size_t)NS * NSLICE * CANDN]; // per (sample,slice) sorted keys
__device__ u64   g_cand[NS * CANDN];                 // per sample global top-160
__device__ float g_crow[(size_t)NS * CANDN * NS];    // baseline dot rows per (sample,cand)

__device__ __forceinline__ u64 u64min(u64 a, u64 b) { return a < b ? a : b; }
__device__ __forceinline__ u64 u64max(u64 a, u64 b) { return a > b ? a : b; }

// ---------------- K1: Gram matrix G = X X^T ----------------
__global__ void k_gram(const float* __restrict__ X) {
    __shared__ float sx[DIM];
    __shared__ float red[256];
    int b = blockIdx.x, tid = threadIdx.x;
    sx[tid] = X[b * DIM + tid];
    __syncthreads();
    int j = tid & 63, q = tid >> 6;
    const float* xj = X + (size_t)j * DIM + q * 64;
    const float* xb = sx + q * 64;
    float p = 0.f;
#pragma unroll
    for (int k = 0; k < 64; ++k) p += xb[k] * xj[k];
    red[tid] = p;
    __syncthreads();
    if (tid < 64)
        g_G[b * NS + tid] = red[tid] + red[tid + 64] + red[tid + 128] + red[tid + 192];
}

// ---------------- K2: D = X V^T and vnorms ----------------
// 782 CTAs x 256 thr; tile 64 samples x 128 nodes; per-thread 4x8 accumulator.
__global__ __launch_bounds__(256) void k_gemm(const float* __restrict__ X, const float* __restrict__ V) {
    __shared__ __align__(16) float sX[32][68];    // [k][s]
    __shared__ __align__(16) float sV[32][132];   // [k][j]
    int tid = threadIdx.x;
    int j0 = blockIdx.x * NPC;
    int nvalid = N_NODES - j0; if (nvalid > NPC) nvalid = NPC;

    int sg = tid & 15, ng = tid >> 4;
    int xs = tid & 63, xf = tid >> 6;     // X loader: row xs, f4-group pair xf
    int vj = tid & 127, vh = tid >> 7;    // V loader: row vj, k-half vh
    bool vok = (vj < nvalid);
    const float* Vrow = V + (size_t)(vok ? (j0 + vj) : 0) * DIM;
    const float* Xrow = X + (size_t)xs * DIM;

    float acc[4][8];
#pragma unroll
    for (int a = 0; a < 4; ++a)
#pragma unroll
        for (int c = 0; c < 8; ++c) acc[a][c] = 0.f;
    float vnacc = 0.f;

    for (int kc = 0; kc < DIM; kc += 32) {
#pragma unroll
        for (int u = 0; u < 2; ++u) {
            int kof = (xf * 2 + u) * 4;
            float4 f = *(const float4*)(Xrow + kc + kof);
            sX[kof + 0][xs] = f.x; sX[kof + 1][xs] = f.y;
            sX[kof + 2][xs] = f.z; sX[kof + 3][xs] = f.w;
        }
#pragma unroll
        for (int u = 0; u < 4; ++u) {
            int kof = vh * 16 + u * 4;
            float4 f = vok ? *(const float4*)(Vrow + kc + kof) : make_float4(0.f, 0.f, 0.f, 0.f);
            sV[kof + 0][vj] = f.x; sV[kof + 1][vj] = f.y;
            sV[kof + 2][vj] = f.z; sV[kof + 3][vj] = f.w;
            vnacc += f.x * f.x + f.y * f.y + f.z * f.z + f.w * f.w;
        }
        __syncthreads();
#pragma unroll
        for (int kk = 0; kk < 32; ++kk) {
            float4 xv = *(const float4*)&sX[kk][sg * 4];
            float4 va = *(const float4*)&sV[kk][ng * 8];
            float4 vb = *(const float4*)&sV[kk][ng * 8 + 4];
            acc[0][0] += xv.x * va.x; acc[0][1] += xv.x * va.y; acc[0][2] += xv.x * va.z; acc[0][3] += xv.x * va.w;
            acc[0][4] += xv.x * vb.x; acc[0][5] += xv.x * vb.y; acc[0][6] += xv.x * vb.z; acc[0][7] += xv.x * vb.w;
            acc[1][0] += xv.y * va.x; acc[1][1] += xv.y * va.y; acc[1][2] += xv.y * va.z; acc[1][3] += xv.y * va.w;
            acc[1][4] += xv.y * vb.x; acc[1][5] += xv.y * vb.y; acc[1][6] += xv.y * vb.z; acc[1][7] += xv.y * vb.w;
            acc[2][0] += xv.z * va.x; acc[2][1] += xv.z * va.y; acc[2][2] += xv.z * va.z; acc[2][3] += xv.z * va.w;
            acc[2][4] += xv.z * vb.x; acc[2][5] += xv.z * vb.y; acc[2][6] += xv.z * vb.z; acc[2][7] += xv.z * vb.w;
            acc[3][0] += xv.w * va.x; acc[3][1] += xv.w * va.y; acc[3][2] += xv.w * va.z; acc[3][3] += xv.w * va.w;
            acc[3][4] += xv.w * vb.x; acc[3][5] += xv.w * vb.y; acc[3][6] += xv.w * vb.z; acc[3][7] += xv.w * vb.w;
        }
        __syncthreads();
    }

    // combine the two per-row vnorm halves via smem (sX reusable after final sync)
    float* svn = (float*)sX;
    if (vh == 1) svn[vj] = vnacc;
    __syncthreads();
    if (vh == 0 && vok) g_vn[j0 + vj] = vnacc + svn[vj];

    int jb = ng * 8;
    if (jb < nvalid) {
        bool full = (jb + 8 <= nvalid);
#pragma unroll
        for (int a = 0; a < 4; ++a) {
            int s = sg * 4 + a;
            float* dst = g_D + (size_t)s * N_NODES + j0 + jb;
            if (full) {
                *(float4*)dst       = make_float4(acc[a][0], acc[a][1], acc[a][2], acc[a][3]);
                *(float4*)(dst + 4) = make_float4(acc[a][4], acc[a][5], acc[a][6], acc[a][7]);
            } else {
                for (int c = 0; c < 8; ++c) if (jb + c < nvalid) dst[c] = acc[a][c];
            }
        }
    }
}

// ---------------- K3: per (sample,slice) top-CANDN via register PQ + bitonic ----------------
__global__ __launch_bounds__(256) void k_cand() {
    __shared__ u64 keys[4096];
    int slice = blockIdx.x, i = blockIdx.y, tid = threadIdx.x;
    float xn = __ldg(&g_G[i * NS + i]);
    const float* Drow = g_D + (size_t)i * N_NODES;
    int base = slice * SLICEN, jend = base + SLICEN;

    u64 K[TK];
#pragma unroll
    for (int m = 0; m < TK; ++m) K[m] = ~0ull;

    for (int j = base + tid; j < jend; j += 1024) {
        float d[4]; int jj[4]; bool ok[4];
#pragma unroll
        for (int q = 0; q < 4; ++q) {
            jj[q] = j + q * 256;
            ok[q] = jj[q] < jend;
            int js = ok[q] ? jj[q] : base;
            d[q] = xn - 2.f * __ldg(&Drow[js]) + __ldg(&g_vn[js]);
        }
#pragma unroll
        for (int q = 0; q < 4; ++q) {
            if (ok[q]) {
                u64 key = ((u64)__float_as_uint(d[q]) << 32) | (unsigned)jj[q];
                if (key < K[TK - 1]) {
                    K[TK - 1] = key;
#pragma unroll
                    for (int m = TK - 1; m > 0; --m) {
                        u64 a = u64min(K[m - 1], K[m]);
                        u64 b = u64max(K[m - 1], K[m]);
                        K[m - 1] = a; K[m] = b;
                    }
                }
            }
        }
    }
#pragma unroll
    for (int m = 0; m < TK; ++m) keys[tid * TK + m] = K[m];
    __syncthreads();
    for (int k = 2; k <= 4096; k <<= 1) {
        for (int j2 = k >> 1; j2 > 0; j2 >>= 1) {
            for (int t = tid; t < 4096; t += 256) {
                int ixj = t ^ j2;
                if (ixj > t) {
                    u64 a = keys[t], b = keys[ixj];
                    bool up = ((t & k) == 0);
                    if ((a > b) == up) { keys[t] = b; keys[ixj] = a; }
                }
            }
            __syncthreads();
        }
    }
    if (tid < CANDN)
        g_scand[((size_t)i * NSLICE + slice) * CANDN + tid] = keys[tid];
}

// ---------------- K3b: merge slices -> global top-160, gather baseline dot rows ----------------
__global__ __launch_bounds__(256) void k_merge() {
    __shared__ u64 keys[2048];
    __shared__ unsigned cidx[CANDN];
    int i = blockIdx.x, tid = threadIdx.x;
    const int TOT = NSLICE * CANDN;   // 1280
    for (int t = tid; t < 2048; t += 256)
        keys[t] = (t < TOT) ? __ldg(&g_scand[(size_t)i * TOT + t]) : ~0ull;
    __syncthreads();
    for (int k = 2; k <= 2048; k <<= 1) {
        for (int j2 = k >> 1; j2 > 0; j2 >>= 1) {
            for (int t = tid; t < 2048; t += 256) {
                int ixj = t ^ j2;
                if (ixj > t) {
                    u64 a = keys[t], b = keys[ixj];
                    bool up = ((t & k) == 0);
                    if ((a > b) == up) { keys[t] = b; keys[ixj] = a; }
                }
            }
            __syncthreads();
        }
    }
    if (tid < CANDN) {
        g_cand[i * CANDN + tid] = keys[tid];
        cidx[tid] = (unsigned)keys[tid];
    }
    __syncthreads();
    // gather exact baseline dot rows: g_crow[i][c][t] = g_D[t][cand_c]
    for (int idx = tid; idx < CANDN * NS; idx += 256) {
        int c = idx >> 6, t = idx & 63;
        g_crow[((size_t)i * CANDN + c) * NS + t] = __ldg(&g_D[(size_t)t * N_NODES + cidx[c]]);
    }
}

// ---------------- K4: sequential 64-step BMU loop, warp-replicated selection ----------------
__global__ __launch_bounds__(128) void k_seq(const int* __restrict__ itp, float* __restrict__ out) {
    __shared__ float    mdt[64 * 129];   // mod_DT[t][m], pad 129 (33 KB)
    __shared__ float    mvn[MODCAP];
    __shared__ int      midx[MODCAP];
    __shared__ unsigned bm[BMW];

    int tid = threadIdx.x;
    int lane = tid & 31, wid = tid >> 5;

    for (int t = tid; t < BMW; t += 128) bm[t] = 0;
    int it = itp ? __ldg(itp) : 0;
    float eb = 1.0f / (float)(it + 2);
    float en = 1.0f / (float)((it + 1) * 100);

    u64 kc_[5];
#pragma unroll
    for (int q = 0; q < 5; ++q) kc_[q] = __ldg(&g_cand[q * 32 + lane]);
    float gr0 = __ldg(&g_G[lane]);
    float gr1 = __ldg(&g_G[32 + lane]);
    int nmod = 0;
    __syncthreads();

    for (int i = 0; i < NS; ++i) {
        float xn = __shfl_sync(0xffffffffu, (i < 32) ? gr0 : gr1, i & 31);

        // ---- selection (replicated per warp) ----
        u64 k1 = ~0ull, k2 = ~0ull;
#pragma unroll
        for (int q = 0; q < 5; ++q) {
            u64 key = kc_[q];
            unsigned idx = (unsigned)key;
            if (!((bm[idx >> 5] >> (idx & 31)) & 1u)) {
                if (key < k1) { k2 = k1; k1 = key; } else if (key < k2) k2 = key;
            }
        }
#pragma unroll
        for (int q = 0; q < 4; ++q) {
            int m = q * 32 + lane;
            if (m < nmod) {
                float d2 = xn - 2.f * mdt[i * 129 + m] + mvn[m];
                u64 key = ((u64)__float_as_uint(d2) << 32) | (unsigned)midx[m];
                if (key < k1) { k2 = k1; k1 = key; } else if (key < k2) k2 = key;
            }
        }
#pragma unroll
        for (int off = 16; off; off >>= 1) {
            u64 b1 = __shfl_xor_sync(0xffffffffu, k1, off);
            u64 b2 = __shfl_xor_sync(0xffffffffu, k2, off);
            u64 m1 = u64min(k1, b1);
            u64 m2 = u64min(u64max(k1, b1), u64min(k2, b2));
            k1 = m1; k2 = m2;
        }
        unsigned nb = (unsigned)k1, nsd = (unsigned)k2;

        // slot lookup in mod table (replicated)
        int slot_b = -1, slot_s = -1;
#pragma unroll
        for (int q = 0; q < 4; ++q) {
            int m = q * 32 + lane;
            int v = (m < nmod) ? midx[m] : -1;
            unsigned bb = __ballot_sync(0xffffffffu, v == (int)nb);
            unsigned bs = __ballot_sync(0xffffffffu, v == (int)nsd);
            if (bb) slot_b = q * 32 + __ffs(bb) - 1;
            if (bs) slot_s = q * 32 + __ffs(bs) - 1;
        }
        bool newb = (slot_b < 0), news = (slot_s < 0);
        if (newb) slot_b = nmod;
        if (news) slot_s = nmod + (newb ? 1 : 0);

        // candidate rank lookup (valid whenever node is new)
        int rank_b = -1, rank_s = -1;
#pragma unroll
        for (int q = 0; q < 5; ++q) {
            unsigned bb = __ballot_sync(0xffffffffu, kc_[q] == k1);
            unsigned bs = __ballot_sync(0xffffffffu, kc_[q] == k2);
            if (bb) rank_b = q * 32 + __ffs(bb) - 1;
            if (bs) rank_s = q * 32 + __ffs(bs) - 1;
        }

        __syncthreads();   // selection reads done before any mutation

        // prefetch next-step candidate keys and Gram row
        float ngr0 = gr0, ngr1 = gr1;
        if (i + 1 < NS) {
#pragma unroll
            for (int q = 0; q < 5; ++q) kc_[q] = __ldg(&g_cand[(size_t)(i + 1) * CANDN + q * 32 + lane]);
            ngr0 = __ldg(&g_G[(i + 1) * NS + lane]);
            ngr1 = __ldg(&g_G[(i + 1) * NS + 32 + lane]);
        }

        if (wid == 2 && lane == 0) {
            out[2 * i]     = sqrtf(__uint_as_float((unsigned)(k1 >> 32)) + 1e-12f);
            out[2 * i + 1] = sqrtf(__uint_as_float((unsigned)(k2 >> 32)) + 1e-12f);
        }

        if (wid == 0) {   // BMU row update
            float om = 1.f - eb;
            float o0, o1;
            if (newb) {
                const float* row = g_crow + ((size_t)i * CANDN + rank_b) * NS;
                o0 = __ldg(&row[lane]);
                o1 = __ldg(&row[32 + lane]);
            } else {
                o0 = mdt[lane * 129 + slot_b];
                o1 = mdt[(32 + lane) * 129 + slot_b];
            }
            float oi = __shfl_sync(0xffffffffu, (i < 32) ? o0 : o1, i & 31);
            if (lane == 0) {
                float vno = newb ? __ldg(&g_vn[nb]) : mvn[slot_b];
                mvn[slot_b] = om * om * vno + 2.f * eb * om * oi + eb * eb * xn;
                if (newb) { midx[slot_b] = (int)nb; atomicOr(&bm[nb >> 5], 1u << (nb & 31)); }
            }
            mdt[lane * 129 + slot_b]        = om * o0 + eb * gr0;
            mdt[(32 + lane) * 129 + slot_b] = om * o1 + eb * gr1;
        }
        if (wid == 1) {   // sBMU row update
            float om = 1.f - en;
            float o0, o1;
            if (news) {
                const float* row = g_crow + ((size_t)i * CANDN + rank_s) * NS;
                o0 = __ldg(&row[lane]);
                o1 = __ldg(&row[32 + lane]);
            } else {
                o0 = mdt[lane * 129 + slot_s];
                o1 = mdt[(32 + lane) * 129 + slot_s];
            }
            float oi = __shfl_sync(0xffffffffu, (i < 32) ? o0 : o1, i & 31);
            if (lane == 0) {
                float vno = news ? __ldg(&g_vn[nsd]) : mvn[slot_s];
                mvn[slot_s] = om * om * vno + 2.f * en * om * oi + en * en * xn;
                if (news) { midx[slot_s] = (int)nsd; atomicOr(&bm[nsd >> 5], 1u << (nsd & 31)); }
            }
            mdt[lane * 129 + slot_s]        = om * o0 + en * gr0;
            mdt[(32 + lane) * 129 + slot_s] = om * o1 + en * gr1;
        }

        nmod += (newb ? 1 : 0) + (news ? 1 : 0);
        gr0 = ngr0; gr1 = ngr1;
        __syncthreads();   // mutations visible before next selection
    }
}

extern "C" void kernel_launch(void* const* d_in, const int* in_sizes, int n_in,
                              void* d_out, int out_size) {
    const float* X = (const float*)d_in[0];     // data [64,256]
    const float* V = (const float*)d_in[1];     // V [100000,256]
    const int* itp = (n_in > 3) ? (const int*)d_in[3] : nullptr;
    float* out = (float*)d_out;                 // [64,2]

    k_gram<<<NS, 256>>>(X);
    k_gemm<<<(N_NODES + NPC - 1) / NPC, 256>>>(X, V);
    k_cand<<<dim3(NSLICE, NS), 256>>>();
    k_merge<<<NS, 256>>>();
    k_seq<<<1, 128>>>(itp, out);
}

// round 4
// speedup vs baseline: 4.3498x; 1.0291x over previous
#include <cuda_runtime.h>
#include <stdint.h>

#define N_NODES 100000
#define DIM     256
#define NS      64
#define NPC     128                 // nodes per CTA in k_gemm
#define NSLICE  8                   // slices per sample in k_cand
#define SLICEN  (N_NODES / NSLICE)  // 12500
#define CANDN   160
#define TK      16
#define MODCAP  128
#define BMW     (N_NODES / 32)      // 3125

typedef unsigned long long u64;

// -------- scratch (static device globals; no runtime allocation) --------
__device__ float g_D[(size_t)NS * N_NODES];            // D[s][j] = dot(x_s, V_j)
__device__ float g_DT[(size_t)N_NODES * NS];           // DT[j][s] = dot(x_s, V_j) (transposed)
__device__ float g_vn[N_NODES];                        // ||V_j||^2
__device__ float g_G[NS * NS];                         // Gram of X (diag = ||x||^2)
__device__ u64   g_scand[(size_t)NS * NSLICE * CANDN]; // per (sample,slice) sorted keys
__device__ u64   g_cand[NS * CANDN];                   // per sample global top-160

__device__ __forceinline__ u64 u64min(u64 a, u64 b) { return a < b ? a : b; }
__device__ __forceinline__ u64 u64max(u64 a, u64 b) { return a > b ? a : b; }

__device__ __forceinline__ u64 f2fma(u64 a, u64 b, u64 c) {
    u64 d;
    asm("fma.rn.f32x2 %0, %1, %2, %3;" : "=l"(d) : "l"(a), "l"(b), "l"(c));
    return d;
}
__device__ __forceinline__ u64 fpack(float x) {
    u64 d;
    asm("mov.b64 %0, {%1, %1};" : "=l"(d) : "r"(__float_as_uint(x)));
    return d;
}
__device__ __forceinline__ void funpack(u64 v, float& lo, float& hi) {
    unsigned a, b;
    asm("mov.b64 {%0, %1}, %2;" : "=r"(a), "=r"(b) : "l"(v));
    lo = __uint_as_float(a); hi = __uint_as_float(b);
}

// ---------------- K1: Gram matrix G = X X^T ----------------
__global__ void k_gram(const float* __restrict__ X) {
    __shared__ float sx[DIM];
    __shared__ float red[256];
    int b = blockIdx.x, tid = threadIdx.x;
    sx[tid] = X[b * DIM + tid];
    __syncthreads();
    int j = tid & 63, q = tid >> 6;
    const float* xj = X + (size_t)j * DIM + q * 64;
    const float* xb = sx + q * 64;
    float p = 0.f;
#pragma unroll
    for (int k = 0; k < 64; ++k) p += xb[k] * xj[k];
    red[tid] = p;
    __syncthreads();
    if (tid < 64)
        g_G[b * NS + tid] = red[tid] + red[tid + 64] + red[tid + 128] + red[tid + 192];
}

// ---------------- K2: D = X V^T (+ transposed DT) and vnorms; FFMA2 inner loop ----------------
__global__ __launch_bounds__(256) void k_gemm(const float* __restrict__ X, const float* __restrict__ V) {
    __shared__ __align__(16) float sX[32][68];    // [k][s]
    __shared__ __align__(16) float sV[32][132];   // [k][j]
    int tid = threadIdx.x;
    int j0 = blockIdx.x * NPC;
    int nvalid = N_NODES - j0; if (nvalid > NPC) nvalid = NPC;

    int sg = tid & 15, ng = tid >> 4;
    int xs = tid & 63, xf = tid >> 6;     // X loader
    int vj = tid & 127, vh = tid >> 7;    // V loader
    bool vok = (vj < nvalid);
    const float* Vrow = V + (size_t)(vok ? (j0 + vj) : 0) * DIM;
    const float* Xrow = X + (size_t)xs * DIM;

    u64 acc[4][4];   // [sample a][node-pair p] packed f32x2
#pragma unroll
    for (int a = 0; a < 4; ++a)
#pragma unroll
        for (int p = 0; p < 4; ++p) acc[a][p] = 0ull;
    float vnacc = 0.f;

    for (int kc = 0; kc < DIM; kc += 32) {
#pragma unroll
        for (int u = 0; u < 2; ++u) {
            int kof = (xf * 2 + u) * 4;
            float4 f = *(const float4*)(Xrow + kc + kof);
            sX[kof + 0][xs] = f.x; sX[kof + 1][xs] = f.y;
            sX[kof + 2][xs] = f.z; sX[kof + 3][xs] = f.w;
        }
#pragma unroll
        for (int u = 0; u < 4; ++u) {
            int kof = vh * 16 + u * 4;
            float4 f = vok ? *(const float4*)(Vrow + kc + kof) : make_float4(0.f, 0.f, 0.f, 0.f);
            sV[kof + 0][vj] = f.x; sV[kof + 1][vj] = f.y;
            sV[kof + 2][vj] = f.z; sV[kof + 3][vj] = f.w;
            vnacc += f.x * f.x + f.y * f.y + f.z * f.z + f.w * f.w;
        }
        __syncthreads();
#pragma unroll
        for (int kk = 0; kk < 32; ++kk) {
            float4 xv = *(const float4*)&sX[kk][sg * 4];
            ulonglong2 va = *(const ulonglong2*)&sV[kk][ng * 8];
            ulonglong2 vb = *(const ulonglong2*)&sV[kk][ng * 8 + 4];
            u64 x0 = fpack(xv.x), x1 = fpack(xv.y), x2 = fpack(xv.z), x3 = fpack(xv.w);
            acc[0][0] = f2fma(x0, va.x, acc[0][0]); acc[0][1] = f2fma(x0, va.y, acc[0][1]);
            acc[0][2] = f2fma(x0, vb.x, acc[0][2]); acc[0][3] = f2fma(x0, vb.y, acc[0][3]);
            acc[1][0] = f2fma(x1, va.x, acc[1][0]); acc[1][1] = f2fma(x1, va.y, acc[1][1]);
            acc[1][2] = f2fma(x1, vb.x, acc[1][2]); acc[1][3] = f2fma(x1, vb.y, acc[1][3]);
            acc[2][0] = f2fma(x2, va.x, acc[2][0]); acc[2][1] = f2fma(x2, va.y, acc[2][1]);
            acc[2][2] = f2fma(x2, vb.x, acc[2][2]); acc[2][3] = f2fma(x2, vb.y, acc[2][3]);
            acc[3][0] = f2fma(x3, va.x, acc[3][0]); acc[3][1] = f2fma(x3, va.y, acc[3][1]);
            acc[3][2] = f2fma(x3, vb.x, acc[3][2]); acc[3][3] = f2fma(x3, vb.y, acc[3][3]);
        }
        __syncthreads();
    }

    // combine the two per-row vnorm halves via smem (sX reusable after last sync)
    float* svn = (float*)sX;
    if (vh == 1) svn[vj] = vnacc;
    __syncthreads();
    if (vh == 0 && vok) g_vn[j0 + vj] = vnacc + svn[vj];

    // unpack accumulators
    float accf[4][8];
#pragma unroll
    for (int a = 0; a < 4; ++a)
#pragma unroll
        for (int p = 0; p < 4; ++p) funpack(acc[a][p], accf[a][2 * p], accf[a][2 * p + 1]);

    int jb = ng * 8;
    if (jb < nvalid) {
        bool full = (jb + 8 <= nvalid);
        // sample-major g_D
#pragma unroll
        for (int a = 0; a < 4; ++a) {
            int s = sg * 4 + a;
            float* dst = g_D + (size_t)s * N_NODES + j0 + jb;
            if (full) {
                *(float4*)dst       = make_float4(accf[a][0], accf[a][1], accf[a][2], accf[a][3]);
                *(float4*)(dst + 4) = make_float4(accf[a][4], accf[a][5], accf[a][6], accf[a][7]);
            } else {
                for (int c = 0; c < 8; ++c) if (jb + c < nvalid) dst[c] = accf[a][c];
            }
        }
        // node-major g_DT (contiguous 64-float row per node)
#pragma unroll
        for (int c = 0; c < 8; ++c) {
            if (full || jb + c < nvalid) {
                *(float4*)&g_DT[(size_t)(j0 + jb + c) * NS + sg * 4] =
                    make_float4(accf[0][c], accf[1][c], accf[2][c], accf[3][c]);
            }
        }
    }
}

// ---------------- K3: per (sample,slice) top-CANDN via register PQ + bitonic ----------------
__global__ __launch_bounds__(256) void k_cand() {
    __shared__ u64 keys[4096];
    int slice = blockIdx.x, i = blockIdx.y, tid = threadIdx.x;
    float xn = __ldg(&g_G[i * NS + i]);
    const float* Drow = g_D + (size_t)i * N_NODES;
    int base = slice * SLICEN, jend = base + SLICEN;

    u64 K[TK];
#pragma unroll
    for (int m = 0; m < TK; ++m) K[m] = ~0ull;

    for (int j = base + tid; j < jend; j += 1024) {
        float d[4]; int jj[4]; bool ok[4];
#pragma unroll
        for (int q = 0; q < 4; ++q) {
            jj[q] = j + q * 256;
            ok[q] = jj[q] < jend;
            int js = ok[q] ? jj[q] : base;
            d[q] = xn - 2.f * __ldg(&Drow[js]) + __ldg(&g_vn[js]);
        }
#pragma unroll
        for (int q = 0; q < 4; ++q) {
            if (ok[q]) {
                u64 key = ((u64)__float_as_uint(d[q]) << 32) | (unsigned)jj[q];
                if (key < K[TK - 1]) {
                    K[TK - 1] = key;
#pragma unroll
                    for (int m = TK - 1; m > 0; --m) {
                        u64 a = u64min(K[m - 1], K[m]);
                        u64 b = u64max(K[m - 1], K[m]);
                        K[m - 1] = a; K[m] = b;
                    }
                }
            }
        }
    }
#pragma unroll
    for (int m = 0; m < TK; ++m) keys[tid * TK + m] = K[m];
    __syncthreads();
    for (int k = 2; k <= 4096; k <<= 1) {
        for (int j2 = k >> 1; j2 > 0; j2 >>= 1) {
            for (int t = tid; t < 4096; t += 256) {
                int ixj = t ^ j2;
                if (ixj > t) {
                    u64 a = keys[t], b = keys[ixj];
                    bool up = ((t & k) == 0);
                    if ((a > b) == up) { keys[t] = b; keys[ixj] = a; }
                }
            }
            __syncthreads();
        }
    }
    if (tid < CANDN)
        g_scand[((size_t)i * NSLICE + slice) * CANDN + tid] = keys[tid];
}

// ---------------- K3b: merge slices -> global top-160 ----------------
__global__ __launch_bounds__(256) void k_merge() {
    __shared__ u64 keys[2048];
    int i = blockIdx.x, tid = threadIdx.x;
    const int TOT = NSLICE * CANDN;   // 1280
    for (int t = tid; t < 2048; t += 256)
        keys[t] = (t < TOT) ? __ldg(&g_scand[(size_t)i * TOT + t]) : ~0ull;
    __syncthreads();
    for (int k = 2; k <= 2048; k <<= 1) {
        for (int j2 = k >> 1; j2 > 0; j2 >>= 1) {
            for (int t = tid; t < 2048; t += 256) {
                int ixj = t ^ j2;
                if (ixj > t) {
                    u64 a = keys[t], b = keys[ixj];
                    bool up = ((t & k) == 0);
                    if ((a > b) == up) { keys[t] = b; keys[ixj] = a; }
                }
            }
            __syncthreads();
        }
    }
    if (tid < CANDN) g_cand[i * CANDN + tid] = keys[tid];
}

// ---------------- K4: sequential 64-step BMU loop, 2 warps ----------------
__global__ __launch_bounds__(64) void k_seq(const int* __restrict__ itp, float* __restrict__ out) {
    __shared__ float    mdt[64 * 129];   // mod_DT[t][m], pad 129
    __shared__ float    mvn[MODCAP];
    __shared__ int      midx[MODCAP];
    __shared__ unsigned bm[BMW];

    int tid = threadIdx.x;
    int lane = tid & 31, wid = tid >> 5;

    for (int t = tid; t < BMW; t += 64) bm[t] = 0;
    int it = itp ? __ldg(itp) : 0;
    float eb = 1.0f / (float)(it + 2);
    float en = 1.0f / (float)((it + 1) * 100);

    u64 kc_[5];
#pragma unroll
    for (int q = 0; q < 5; ++q) kc_[q] = __ldg(&g_cand[q * 32 + lane]);
    float gr0 = __ldg(&g_G[lane]);
    float gr1 = __ldg(&g_G[32 + lane]);
    int nmod = 0;
    __syncthreads();

    for (int i = 0; i < NS; ++i) {
        float xn = __shfl_sync(0xffffffffu, (i < 32) ? gr0 : gr1, i & 31);

        // ---- selection (replicated per warp) ----
        u64 k1 = ~0ull, k2 = ~0ull;
#pragma unroll
        for (int q = 0; q < 5; ++q) {
            u64 key = kc_[q];
            unsigned idx = (unsigned)key;
            if (!((bm[idx >> 5] >> (idx & 31)) & 1u)) {
                if (key < k1) { k2 = k1; k1 = key; } else if (key < k2) k2 = key;
            }
        }
#pragma unroll
        for (int q = 0; q < 4; ++q) {
            int m = q * 32 + lane;
            if (m < nmod) {
                float d2 = xn - 2.f * mdt[i * 129 + m] + mvn[m];
                u64 key = ((u64)__float_as_uint(d2) << 32) | (unsigned)midx[m];
                if (key < k1) { k2 = k1; k1 = key; } else if (key < k2) k2 = key;
            }
        }
#pragma unroll
        for (int off = 16; off; off >>= 1) {
            u64 b1 = __shfl_xor_sync(0xffffffffu, k1, off);
            u64 b2 = __shfl_xor_sync(0xffffffffu, k2, off);
            u64 m1 = u64min(k1, b1);
            u64 m2 = u64min(u64max(k1, b1), u64min(k2, b2));
            k1 = m1; k2 = m2;
        }
        unsigned nb = (unsigned)k1, nsd = (unsigned)k2;

        // slot lookup in mod table (replicated)
        int slot_b = -1, slot_s = -1;
#pragma unroll
        for (int q = 0; q < 4; ++q) {
            int m = q * 32 + lane;
            int v = (m < nmod) ? midx[m] : -1;
            unsigned bb = __ballot_sync(0xffffffffu, v == (int)nb);
            unsigned bs = __ballot_sync(0xffffffffu, v == (int)nsd);
            if (bb) slot_b = q * 32 + __ffs(bb) - 1;
            if (bs) slot_s = q * 32 + __ffs(bs) - 1;
        }
        bool newb = (slot_b < 0), news = (slot_s < 0);
        if (newb) slot_b = nmod;
        if (news) slot_s = nmod + (newb ? 1 : 0);

        __syncthreads();   // selection reads done before any mutation

        // prefetch next-step candidate keys and Gram row
        float ngr0 = gr0, ngr1 = gr1;
        if (i + 1 < NS) {
#pragma unroll
            for (int q = 0; q < 5; ++q) kc_[q] = __ldg(&g_cand[(size_t)(i + 1) * CANDN + q * 32 + lane]);
            ngr0 = __ldg(&g_G[(i + 1) * NS + lane]);
            ngr1 = __ldg(&g_G[(i + 1) * NS + 32 + lane]);
        }

        if (wid == 0) {   // BMU row update
            if (lane == 0) {
                out[2 * i]     = sqrtf(__uint_as_float((unsigned)(k1 >> 32)) + 1e-12f);
                out[2 * i + 1] = sqrtf(__uint_as_float((unsigned)(k2 >> 32)) + 1e-12f);
            }
            float om = 1.f - eb;
            float o0, o1;
            if (newb) {
                o0 = __ldg(&g_DT[(size_t)nb * NS + lane]);
                o1 = __ldg(&g_DT[(size_t)nb * NS + 32 + lane]);
            } else {
                o0 = mdt[lane * 129 + slot_b];
                o1 = mdt[(32 + lane) * 129 + slot_b];
            }
            float oi = __shfl_sync(0xffffffffu, (i < 32) ? o0 : o1, i & 31);
            if (lane == 0) {
                float vno = newb ? __ldg(&g_vn[nb]) : mvn[slot_b];
                mvn[slot_b] = om * om * vno + 2.f * eb * om * oi + eb * eb * xn;
                if (newb) { midx[slot_b] = (int)nb; atomicOr(&bm[nb >> 5], 1u << (nb & 31)); }
            }
            mdt[lane * 129 + slot_b]        = om * o0 + eb * gr0;
            mdt[(32 + lane) * 129 + slot_b] = om * o1 + eb * gr1;
        } else {          // sBMU row update
            float om = 1.f - en;
            float o0, o1;
            if (news) {
                o0 = __ldg(&g_DT[(size_t)nsd * NS + lane]);
                o1 = __ldg(&g_DT[(size_t)nsd * NS + 32 + lane]);
            } else {
                o0 = mdt[lane * 129 + slot_s];
                o1 = mdt[(32 + lane) * 129 + slot_s];
            }
            float oi = __shfl_sync(0xffffffffu, (i < 32) ? o0 : o1, i & 31);
            if (lane == 0) {
                float vno = news ? __ldg(&g_vn[nsd]) : mvn[slot_s];
                mvn[slot_s] = om * om * vno + 2.f * en * om * oi + en * en * xn;
                if (news) { midx[slot_s] = (int)nsd; atomicOr(&bm[nsd >> 5], 1u << (nsd & 31)); }
            }
            mdt[lane * 129 + slot_s]        = om * o0 + en * gr0;
            mdt[(32 + lane) * 129 + slot_s] = om * o1 + en * gr1;
        }

        nmod += (newb ? 1 : 0) + (news ? 1 : 0);
        gr0 = ngr0; gr1 = ngr1;
        __syncthreads();   // mutations visible before next selection
    }
}

extern "C" void kernel_launch(void* const* d_in, const int* in_sizes, int n_in,
                              void* d_out, int out_size) {
    const float* X = (const float*)d_in[0];     // data [64,256]
    const float* V = (const float*)d_in[1];     // V [100000,256]
    const int* itp = (n_in > 3) ? (const int*)d_in[3] : nullptr;
    float* out = (float*)d_out;                 // [64,2]

    k_gram<<<NS, 256>>>(X);
    k_gemm<<<(N_NODES + NPC - 1) / NPC, 256>>>(X, V);
    k_cand<<<dim3(NSLICE, NS), 256>>>();
    k_merge<<<NS, 256>>>();
    k_seq<<<1, 64>>>(itp, out);
}

// round 5
// speedup vs baseline: 4.9269x; 1.1327x over previous
#include <cuda_runtime.h>
#include <stdint.h>

#define N_NODES 100000
#define DIM     256
#define NS      64
#define NPC     256                 // nodes per CTA in k_gemm
#define NSLICE  8                   // slices per sample in k_cand
#define SLICEN  (N_NODES / NSLICE)  // 12500
#define CANDN   160
#define TK      8
#define MODCAP  128
#define BMW     (N_NODES / 32)      // 3125

typedef unsigned long long u64;

// -------- scratch (static device globals; no runtime allocation) --------
__device__ float g_D[(size_t)NS * N_NODES];            // D[s][j] = dot(x_s, V_j)
__device__ float g_DT[(size_t)N_NODES * NS];           // DT[j][s] (transposed, immutable baseline)
__device__ float g_vn[N_NODES];                        // ||V_j||^2
__device__ float g_G[NS * NS];                         // Gram of X (diag = ||x||^2)
__device__ u64   g_scand[(size_t)NS * NSLICE * CANDN]; // per (sample,slice) sorted keys
__device__ u64   g_cand[NS * CANDN];                   // per sample global top-160

__device__ __forceinline__ u64 u64min(u64 a, u64 b) { return a < b ? a : b; }
__device__ __forceinline__ u64 u64max(u64 a, u64 b) { return a > b ? a : b; }

__device__ __forceinline__ u64 f2fma(u64 a, u64 b, u64 c) {
    u64 d;
    asm("fma.rn.f32x2 %0, %1, %2, %3;" : "=l"(d) : "l"(a), "l"(b), "l"(c));
    return d;
}
__device__ __forceinline__ u64 fpack(float x) {
    u64 d;
    asm("mov.b64 %0, {%1, %1};" : "=l"(d) : "r"(__float_as_uint(x)));
    return d;
}
__device__ __forceinline__ void funpack(u64 v, float& lo, float& hi) {
    unsigned a, b;
    asm("mov.b64 {%0, %1}, %2;" : "=r"(a), "=r"(b) : "l"(v));
    lo = __uint_as_float(a); hi = __uint_as_float(b);
}

// ---------------- K1: Gram matrix G = X X^T ----------------
__global__ void k_gram(const float* __restrict__ X) {
    __shared__ float sx[DIM];
    __shared__ float red[256];
    int b = blockIdx.x, tid = threadIdx.x;
    sx[tid] = X[b * DIM + tid];
    __syncthreads();
    int j = tid & 63, q = tid >> 6;
    const float* xj = X + (size_t)j * DIM + q * 64;
    const float* xb = sx + q * 64;
    float p = 0.f;
#pragma unroll
    for (int k = 0; k < 64; ++k) p += xb[k] * xj[k];
    red[tid] = p;
    __syncthreads();
    if (tid < 64)
        g_G[b * NS + tid] = red[tid] + red[tid + 64] + red[tid + 128] + red[tid + 192];
}

// ---------------- K2: D = X V^T (+ DT) and vnorms; 8x8 FFMA2 tile ----------------
__global__ __launch_bounds__(256) void k_gemm(const float* __restrict__ X, const float* __restrict__ V) {
    __shared__ __align__(16) float sX[32][68];    // [k][s]
    __shared__ __align__(16) float sV[32][260];   // [k][j]
    int tid = threadIdx.x;
    int j0 = blockIdx.x * NPC;
    int nvalid = N_NODES - j0; if (nvalid > NPC) nvalid = NPC;

    int sg = tid & 7, ng = tid >> 3;      // compute mapping: 8 sample-groups x 32 node-groups
    int xs = tid & 63, xf = tid >> 6;     // X loader
    bool vok = tid < nvalid;
    const float* Vrow = V + (size_t)(vok ? (j0 + tid) : 0) * DIM;
    const float* Xrow = X + (size_t)xs * DIM;

    u64 acc[8][4];
#pragma unroll
    for (int a = 0; a < 8; ++a)
#pragma unroll
        for (int p = 0; p < 4; ++p) acc[a][p] = 0ull;
    float vnacc = 0.f;

    for (int kc = 0; kc < DIM; kc += 32) {
#pragma unroll
        for (int u = 0; u < 2; ++u) {
            int kof = xf * 8 + u * 4;
            float4 f = *(const float4*)(Xrow + kc + kof);
            sX[kof + 0][xs] = f.x; sX[kof + 1][xs] = f.y;
            sX[kof + 2][xs] = f.z; sX[kof + 3][xs] = f.w;
        }
#pragma unroll
        for (int u = 0; u < 8; ++u) {
            int kof = u * 4;
            float4 f = vok ? *(const float4*)(Vrow + kc + kof) : make_float4(0.f, 0.f, 0.f, 0.f);
            sV[kof + 0][tid] = f.x; sV[kof + 1][tid] = f.y;
            sV[kof + 2][tid] = f.z; sV[kof + 3][tid] = f.w;
            vnacc += f.x * f.x + f.y * f.y + f.z * f.z + f.w * f.w;
        }
        __syncthreads();
#pragma unroll
        for (int kk = 0; kk < 32; ++kk) {
            float4 xa = *(const float4*)&sX[kk][sg * 8];
            float4 xb = *(const float4*)&sX[kk][sg * 8 + 4];
            ulonglong2 va = *(const ulonglong2*)&sV[kk][ng * 8];
            ulonglong2 vb = *(const ulonglong2*)&sV[kk][ng * 8 + 4];
            u64 xp[8];
            xp[0] = fpack(xa.x); xp[1] = fpack(xa.y); xp[2] = fpack(xa.z); xp[3] = fpack(xa.w);
            xp[4] = fpack(xb.x); xp[5] = fpack(xb.y); xp[6] = fpack(xb.z); xp[7] = fpack(xb.w);
#pragma unroll
            for (int a = 0; a < 8; ++a) {
                acc[a][0] = f2fma(xp[a], va.x, acc[a][0]);
                acc[a][1] = f2fma(xp[a], va.y, acc[a][1]);
                acc[a][2] = f2fma(xp[a], vb.x, acc[a][2]);
                acc[a][3] = f2fma(xp[a], vb.y, acc[a][3]);
            }
        }
        __syncthreads();
    }

    if (vok) g_vn[j0 + tid] = vnacc;

    float accf[8][8];
#pragma unroll
    for (int a = 0; a < 8; ++a)
#pragma unroll
        for (int p = 0; p < 4; ++p) funpack(acc[a][p], accf[a][2 * p], accf[a][2 * p + 1]);

    int jb = ng * 8;
    if (jb < nvalid) {
        bool full = (jb + 8 <= nvalid);
#pragma unroll
        for (int a = 0; a < 8; ++a) {
            int s = sg * 8 + a;
            float* dst = g_D + (size_t)s * N_NODES + j0 + jb;
            if (full) {
                *(float4*)dst       = make_float4(accf[a][0], accf[a][1], accf[a][2], accf[a][3]);
                *(float4*)(dst + 4) = make_float4(accf[a][4], accf[a][5], accf[a][6], accf[a][7]);
            } else {
                for (int c = 0; c < 8; ++c) if (jb + c < nvalid) dst[c] = accf[a][c];
            }
        }
#pragma unroll
        for (int c = 0; c < 8; ++c) {
            if (full || jb + c < nvalid) {
                float* dst = &g_DT[(size_t)(j0 + jb + c) * NS + sg * 8];
                *(float4*)dst       = make_float4(accf[0][c], accf[1][c], accf[2][c], accf[3][c]);
                *(float4*)(dst + 4) = make_float4(accf[4][c], accf[5][c], accf[6][c], accf[7][c]);
            }
        }
    }
}

// ---------------- K3: per (sample,slice) top-CANDN via register PQ + bitonic ----------------
__global__ __launch_bounds__(512) void k_cand() {
    __shared__ u64 keys[4096];
    int slice = blockIdx.x, i = blockIdx.y, tid = threadIdx.x;
    float xn = __ldg(&g_G[i * NS + i]);
    const float* Drow = g_D + (size_t)i * N_NODES;
    int base = slice * SLICEN, jend = base + SLICEN;

    u64 K[TK];
#pragma unroll
    for (int m = 0; m < TK; ++m) K[m] = ~0ull;

    for (int j = base + tid; j < jend; j += 2048) {
        float d[4]; int jj[4]; bool ok[4];
#pragma unroll
        for (int q = 0; q < 4; ++q) {
            jj[q] = j + q * 512;
            ok[q] = jj[q] < jend;
            int js = ok[q] ? jj[q] : base;
            d[q] = xn - 2.f * __ldg(&Drow[js]) + __ldg(&g_vn[js]);
        }
#pragma unroll
        for (int q = 0; q < 4; ++q) {
            if (ok[q]) {
                u64 key = ((u64)__float_as_uint(d[q]) << 32) | (unsigned)jj[q];
                if (key < K[TK - 1]) {
                    K[TK - 1] = key;
#pragma unroll
                    for (int m = TK - 1; m > 0; --m) {
                        u64 a = u64min(K[m - 1], K[m]);
                        u64 b = u64max(K[m - 1], K[m]);
                        K[m - 1] = a; K[m] = b;
                    }
                }
            }
        }
    }
#pragma unroll
    for (int m = 0; m < TK; ++m) keys[tid * TK + m] = K[m];
    __syncthreads();
    for (int k = 2; k <= 4096; k <<= 1) {
        for (int j2 = k >> 1; j2 > 0; j2 >>= 1) {
            for (int t = tid; t < 4096; t += 512) {
                int ixj = t ^ j2;
                if (ixj > t) {
                    u64 a = keys[t], b = keys[ixj];
                    bool up = ((t & k) == 0);
                    if ((a > b) == up) { keys[t] = b; keys[ixj] = a; }
                }
            }
            __syncthreads();
        }
    }
    if (tid < CANDN)
        g_scand[((size_t)i * NSLICE + slice) * CANDN + tid] = keys[tid];
}

// ---------------- K3b: merge 8 sorted lists -> global top-160 (merge network only) ----------------
__global__ __launch_bounds__(512) void k_merge() {
    __shared__ u64 keys[2048];
    int i = blockIdx.x, tid = threadIdx.x;
    for (int t = tid; t < 2048; t += 512) {
        int list = t >> 8, pos = t & 255;
        keys[t] = (pos < CANDN) ? __ldg(&g_scand[((size_t)i * NSLICE + list) * CANDN + pos]) : ~0ull;
    }
    __syncthreads();
#pragma unroll
    for (int L = 0; L < 3; ++L) {
        int npairs = 4 >> L;
        int pairstride = 512 << L;
        // halver: cmp A[i] vs B[255-i], keep min in A
        int nops = npairs << 8;
        for (int t = tid; t < nops; t += 512) {
            int p = t >> 8, ii = t & 255;
            int a = p * pairstride + ii;
            int b = p * pairstride + (pairstride >> 1) + 255 - ii;
            u64 x = keys[a], y = keys[b];
            if (y < x) { keys[a] = y; keys[b] = x; }
        }
        __syncthreads();
        // clean: bitonic merge of each surviving 256-block
        for (int j = 128; j > 0; j >>= 1) {
            int cops = npairs << 7;
            for (int t = tid; t < cops; t += 512) {
                int p = t >> 7, q = t & 127;
                int idx = ((q & ~(j - 1)) << 1) | (q & (j - 1));
                int a = p * pairstride + idx;
                u64 x = keys[a], y = keys[a + j];
                if (y < x) { keys[a] = y; keys[a + j] = x; }
            }
            __syncthreads();
        }
    }
    if (tid < CANDN) g_cand[i * CANDN + tid] = keys[tid];
}

// ---------------- K4: sequential BMU loop, single warp, all-smem + row prefetch ----------------
#define SEQ_SMEM (NS * CANDN * 8 + NS * NS * 4 + 64 * 129 * 4 + MODCAP * 4 + MODCAP * 4 + BMW * 4 + 64)

__global__ __launch_bounds__(128) void k_seq(const int* __restrict__ itp, float* __restrict__ out) {
    extern __shared__ char smraw[];
    u64*      scand = (u64*)smraw;                  // 10240 u64
    float*    sG    = (float*)(scand + NS * CANDN); // 4096 f
    float*    mdt   = sG + NS * NS;                 // 64*129 f : mdt[t][m]
    float*    mvn   = mdt + 64 * 129;               // 128 f
    int*      midx  = (int*)(mvn + MODCAP);         // 128 i
    unsigned* bm    = (unsigned*)(midx + MODCAP);   // 3125 u32

    int tid = threadIdx.x;
    for (int t = tid; t < NS * CANDN; t += 128) scand[t] = __ldg(&g_cand[t]);
    for (int t = tid; t < NS * NS; t += 128) sG[t] = __ldg(&g_G[t]);
    for (int t = tid; t < BMW; t += 128) bm[t] = 0;
    __syncthreads();
    if (tid >= 32) return;   // single warp from here on; no more __syncthreads

    int lane = tid;
    int it = itp ? __ldg(itp) : 0;
    float eb = 1.0f / (float)(it + 2);
    float en = 1.0f / (float)((it + 1) * 100);
    float ebo = 1.f - eb, eno = 1.f - en;

    // prefetch top-4 candidate DT rows + vnorms for sample 0
    float pfa[4], pfb[4], pfvn = 0.f;
#pragma unroll
    for (int r = 0; r < 4; ++r) {
        unsigned idx = (unsigned)scand[r];
        pfa[r] = __ldg(&g_DT[(size_t)idx * NS + lane]);
        pfb[r] = __ldg(&g_DT[(size_t)idx * NS + 32 + lane]);
    }
    if (lane < 4) pfvn = __ldg(&g_vn[(unsigned)scand[lane]]);
    int nmod = 0;

    for (int i = 0; i < NS; ++i) {
        float xn = sG[i * NS + i];

        // ---- selection ----
        u64 kq[5];
        u64 k1 = ~0ull, k2 = ~0ull;
#pragma unroll
        for (int q = 0; q < 5; ++q) {
            u64 key = scand[i * CANDN + q * 32 + lane];
            kq[q] = key;
            unsigned idx = (unsigned)key;
            if (!((bm[idx >> 5] >> (idx & 31)) & 1u)) {
                if (key < k1) { k2 = k1; k1 = key; } else if (key < k2) k2 = key;
            }
        }
#pragma unroll
        for (int q = 0; q < 4; ++q) {
            int m = q * 32 + lane;
            if (m < nmod) {
                float d2 = xn - 2.f * mdt[i * 129 + m] + mvn[m];
                u64 key = ((u64)__float_as_uint(d2) << 32) | (unsigned)midx[m];
                if (key < k1) { k2 = k1; k1 = key; } else if (key < k2) k2 = key;
            }
        }
#pragma unroll
        for (int off = 16; off; off >>= 1) {
            u64 b1 = __shfl_xor_sync(0xffffffffu, k1, off);
            u64 b2 = __shfl_xor_sync(0xffffffffu, k2, off);
            u64 m1 = u64min(k1, b1);
            u64 m2 = u64min(u64max(k1, b1), u64min(k2, b2));
            k1 = m1; k2 = m2;
        }
        unsigned nb = (unsigned)k1, nsd = (unsigned)k2;

        // slot lookup in mod table
        int slot_b = -1, slot_s = -1;
#pragma unroll
        for (int q = 0; q < 4; ++q) {
            int m = q * 32 + lane;
            int v = (m < nmod) ? midx[m] : -1;
            unsigned bb = __ballot_sync(0xffffffffu, v == (int)nb);
            unsigned bs = __ballot_sync(0xffffffffu, v == (int)nsd);
            if (bb) slot_b = q * 32 + __ffs(bb) - 1;
            if (bs) slot_s = q * 32 + __ffs(bs) - 1;
        }
        bool newb = (slot_b < 0), news = (slot_s < 0);
        if (newb) slot_b = nmod;
        if (news) slot_s = nmod + (newb ? 1 : 0);

        // candidate rank lookup (always succeeds for new nodes)
        int rank_b = -1, rank_s = -1;
#pragma unroll
        for (int q = 0; q < 5; ++q) {
            unsigned bb = __ballot_sync(0xffffffffu, kq[q] == k1);
            unsigned bs = __ballot_sync(0xffffffffu, kq[q] == k2);
            if (bb) rank_b = q * 32 + __ffs(bb) - 1;
            if (bs) rank_s = q * 32 + __ffs(bs) - 1;
        }

        if (lane == 0) {
            out[2 * i]     = sqrtf(__uint_as_float((unsigned)(k1 >> 32)) + 1e-12f);
            out[2 * i + 1] = sqrtf(__uint_as_float((unsigned)(k2 >> 32)) + 1e-12f);
        }

        // ---- gather old rows (uniform branches) ----
        float ob0, ob1, os0, os1, vnb, vns;
        if (newb) {
            if (rank_b < 4) {
                ob0 = rank_b == 0 ? pfa[0] : rank_b == 1 ? pfa[1] : rank_b == 2 ? pfa[2] : pfa[3];
                ob1 = rank_b == 0 ? pfb[0] : rank_b == 1 ? pfb[1] : rank_b == 2 ? pfb[2] : pfb[3];
                vnb = __shfl_sync(0xffffffffu, pfvn, rank_b);
            } else {
                ob0 = __ldg(&g_DT[(size_t)nb * NS + lane]);
                ob1 = __ldg(&g_DT[(size_t)nb * NS + 32 + lane]);
                vnb = __ldg(&g_vn[nb]);
            }
        } else {
            ob0 = mdt[lane * 129 + slot_b];
            ob1 = mdt[(32 + lane) * 129 + slot_b];
            vnb = mvn[slot_b];
        }
        if (news) {
            if (rank_s < 4) {
                os0 = rank_s == 0 ? pfa[0] : rank_s == 1 ? pfa[1] : rank_s == 2 ? pfa[2] : pfa[3];
                os1 = rank_s == 0 ? pfb[0] : rank_s == 1 ? pfb[1] : rank_s == 2 ? pfb[2] : pfb[3];
                vns = __shfl_sync(0xffffffffu, pfvn, rank_s);
            } else {
                os0 = __ldg(&g_DT[(size_t)nsd * NS + lane]);
                os1 = __ldg(&g_DT[(size_t)nsd * NS + 32 + lane]);
                vns = __ldg(&g_vn[nsd]);
            }
        } else {
            os0 = mdt[lane * 129 + slot_s];
            os1 = mdt[(32 + lane) * 129 + slot_s];
            vns = mvn[slot_s];
        }
        float obi = __shfl_sync(0xffffffffu, (i < 32) ? ob0 : ob1, i & 31);
        float osi = __shfl_sync(0xffffffffu, (i < 32) ? os0 : os1, i & 31);

        __syncwarp();   // all reads of mdt/mvn/bm complete before mutation

        float gr0 = sG[i * NS + lane], gr1 = sG[i * NS + 32 + lane];
        mdt[lane * 129 + slot_b]        = ebo * ob0 + eb * gr0;
        mdt[(32 + lane) * 129 + slot_b] = ebo * ob1 + eb * gr1;
        mdt[lane * 129 + slot_s]        = eno * os0 + en * gr0;
        mdt[(32 + lane) * 129 + slot_s] = eno * os1 + en * gr1;
        if (lane == 0) {
            mvn[slot_b] = ebo * ebo * vnb + 2.f * eb * ebo * obi + eb * eb * xn;
            mvn[slot_s] = eno * eno * vns + 2.f * en * eno * osi + en * en * xn;
            if (newb) { midx[slot_b] = (int)nb;  bm[nb >> 5]  |= 1u << (nb & 31);  }
            if (news) { midx[slot_s] = (int)nsd; bm[nsd >> 5] |= 1u << (nsd & 31); }
        }
        nmod += (newb ? 1 : 0) + (news ? 1 : 0);

        // prefetch next sample's top-4 candidate rows + vnorms (off critical path)
        if (i + 1 < NS) {
#pragma unroll
            for (int r = 0; r < 4; ++r) {
                unsigned idx = (unsigned)scand[(i + 1) * CANDN + r];
                pfa[r] = __ldg(&g_DT[(size_t)idx * NS + lane]);
                pfb[r] = __ldg(&g_DT[(size_t)idx * NS + 32 + lane]);
            }
            if (lane < 4) pfvn = __ldg(&g_vn[(unsigned)scand[(i + 1) * CANDN + lane]]);
        }
        __syncwarp();   // mutations visible before next selection
    }
}

extern "C" void kernel_launch(void* const* d_in, const int* in_sizes, int n_in,
                              void* d_out, int out_size) {
    const float* X = (const float*)d_in[0];     // data [64,256]
    const float* V = (const float*)d_in[1];     // V [100000,256]
    const int* itp = (n_in > 3) ? (const int*)d_in[3] : nullptr;
    float* out = (float*)d_out;                 // [64,2]

    cudaFuncSetAttribute(k_seq, cudaFuncAttributeMaxDynamicSharedMemorySize, SEQ_SMEM);

    k_gram<<<NS, 256>>>(X);
    k_gemm<<<(N_NODES + NPC - 1) / NPC, 256>>>(X, V);
    k_cand<<<dim3(NSLICE, NS), 512>>>();
    k_merge<<<NS, 512>>>();
    k_seq<<<1, 128, SEQ_SMEM>>>(itp, out);
}

// round 6
// speedup vs baseline: 6.2548x; 1.2695x over previous
#include <cuda_runtime.h>
#include <stdint.h>

#define N_NODES 100000
#define DIM     256
#define NS      64
#define NPC     256                 // nodes per CTA in k_gemm
#define NSLICE  8                   // slices per sample in k_cand
#define SLICEN  (N_NODES / NSLICE)  // 12500
#define CANDN   160
#define TK      8
#define MODCAP  128
#define BMW     (N_NODES / 32)      // 3125
#define HSHN    2048

typedef unsigned long long u64;

// -------- scratch (static device globals; no runtime allocation) --------
__device__ float g_D[(size_t)NS * N_NODES];            // D[s][j] = dot(x_s, V_j)
__device__ float g_DT[(size_t)N_NODES * NS];           // DT[j][s] (transposed, immutable baseline)
__device__ float g_vn[N_NODES];                        // ||V_j||^2
__device__ float g_G[NS * NS];                         // Gram of X (diag = ||x||^2)
__device__ u64   g_scand[(size_t)NS * NSLICE * CANDN]; // per (sample,slice) sorted keys
__device__ u64   g_cand[NS * CANDN];                   // per sample global top-160

__device__ __forceinline__ u64 u64min(u64 a, u64 b) { return a < b ? a : b; }
__device__ __forceinline__ u64 u64max(u64 a, u64 b) { return a > b ? a : b; }

__device__ __forceinline__ u64 f2fma(u64 a, u64 b, u64 c) {
    u64 d;
    asm("fma.rn.f32x2 %0, %1, %2, %3;" : "=l"(d) : "l"(a), "l"(b), "l"(c));
    return d;
}
__device__ __forceinline__ u64 fpack(float x) {
    u64 d;
    asm("mov.b64 %0, {%1, %1};" : "=l"(d) : "r"(__float_as_uint(x)));
    return d;
}
__device__ __forceinline__ void funpack(u64 v, float& lo, float& hi) {
    unsigned a, b;
    asm("mov.b64 {%0, %1}, %2;" : "=r"(a), "=r"(b) : "l"(v));
    lo = __uint_as_float(a); hi = __uint_as_float(b);
}

// ---------------- K1: Gram matrix G = X X^T ----------------
__global__ void k_gram(const float* __restrict__ X) {
    __shared__ float sx[DIM];
    __shared__ float red[256];
    int b = blockIdx.x, tid = threadIdx.x;
    sx[tid] = X[b * DIM + tid];
    __syncthreads();
    int j = tid & 63, q = tid >> 6;
    const float* xj = X + (size_t)j * DIM + q * 64;
    const float* xb = sx + q * 64;
    float p = 0.f;
#pragma unroll
    for (int k = 0; k < 64; ++k) p += xb[k] * xj[k];
    red[tid] = p;
    __syncthreads();
    if (tid < 64)
        g_G[b * NS + tid] = red[tid] + red[tid + 64] + red[tid + 128] + red[tid + 192];
}

// ---------------- K2: D = X V^T (+ DT) and vnorms; 8x8 FFMA2 tile, reg double-buffer ----------------
__global__ __launch_bounds__(256) void k_gemm(const float* __restrict__ X, const float* __restrict__ V) {
    __shared__ __align__(16) float sX[32][68];    // [k][s]
    __shared__ __align__(16) float sV[32][260];   // [k][j]
    int tid = threadIdx.x;
    int j0 = blockIdx.x * NPC;
    int nvalid = N_NODES - j0; if (nvalid > NPC) nvalid = NPC;

    int sg = tid & 7, ng = tid >> 3;      // compute mapping: 8 sample-groups x 32 node-groups
    int xs = tid & 63, xf = tid >> 6;     // X loader
    bool vok = tid < nvalid;
    const float* Vrow = V + (size_t)(vok ? (j0 + tid) : 0) * DIM;
    const float* Xrow = X + (size_t)xs * DIM;

    u64 acc[8][4];
#pragma unroll
    for (int a = 0; a < 8; ++a)
#pragma unroll
        for (int p = 0; p < 4; ++p) acc[a][p] = 0ull;
    float vnacc = 0.f;

    float4 rfx[2], rfv[8];
#pragma unroll
    for (int u = 0; u < 2; ++u) rfx[u] = *(const float4*)(Xrow + xf * 8 + u * 4);
#pragma unroll
    for (int u = 0; u < 8; ++u)
        rfv[u] = vok ? *(const float4*)(Vrow + u * 4) : make_float4(0.f, 0.f, 0.f, 0.f);

    for (int kc = 0; kc < DIM; kc += 32) {
#pragma unroll
        for (int u = 0; u < 2; ++u) {
            int kof = xf * 8 + u * 4;
            sX[kof + 0][xs] = rfx[u].x; sX[kof + 1][xs] = rfx[u].y;
            sX[kof + 2][xs] = rfx[u].z; sX[kof + 3][xs] = rfx[u].w;
        }
#pragma unroll
        for (int u = 0; u < 8; ++u) {
            int kof = u * 4;
            sV[kof + 0][tid] = rfv[u].x; sV[kof + 1][tid] = rfv[u].y;
            sV[kof + 2][tid] = rfv[u].z; sV[kof + 3][tid] = rfv[u].w;
            vnacc += rfv[u].x * rfv[u].x + rfv[u].y * rfv[u].y
                   + rfv[u].z * rfv[u].z + rfv[u].w * rfv[u].w;
        }
        __syncthreads();
        if (kc + 32 < DIM) {   // prefetch next chunk into registers (overlaps compute)
#pragma unroll
            for (int u = 0; u < 2; ++u)
                rfx[u] = *(const float4*)(Xrow + kc + 32 + xf * 8 + u * 4);
#pragma unroll
            for (int u = 0; u < 8; ++u)
                rfv[u] = vok ? *(const float4*)(Vrow + kc + 32 + u * 4)
                             : make_float4(0.f, 0.f, 0.f, 0.f);
        }
#pragma unroll
        for (int kk = 0; kk < 32; ++kk) {
            float4 xa = *(const float4*)&sX[kk][sg * 8];
            float4 xb = *(const float4*)&sX[kk][sg * 8 + 4];
            ulonglong2 va = *(const ulonglong2*)&sV[kk][ng * 8];
            ulonglong2 vb = *(const ulonglong2*)&sV[kk][ng * 8 + 4];
            u64 xp[8];
            xp[0] = fpack(xa.x); xp[1] = fpack(xa.y); xp[2] = fpack(xa.z); xp[3] = fpack(xa.w);
            xp[4] = fpack(xb.x); xp[5] = fpack(xb.y); xp[6] = fpack(xb.z); xp[7] = fpack(xb.w);
#pragma unroll
            for (int a = 0; a < 8; ++a) {
                acc[a][0] = f2fma(xp[a], va.x, acc[a][0]);
                acc[a][1] = f2fma(xp[a], va.y, acc[a][1]);
                acc[a][2] = f2fma(xp[a], vb.x, acc[a][2]);
                acc[a][3] = f2fma(xp[a], vb.y, acc[a][3]);
            }
        }
        __syncthreads();
    }

    if (vok) g_vn[j0 + tid] = vnacc;

    float accf[8][8];
#pragma unroll
    for (int a = 0; a < 8; ++a)
#pragma unroll
        for (int p = 0; p < 4; ++p) funpack(acc[a][p], accf[a][2 * p], accf[a][2 * p + 1]);

    int jb = ng * 8;
    if (jb < nvalid) {
        bool full = (jb + 8 <= nvalid);
#pragma unroll
        for (int a = 0; a < 8; ++a) {
            int s = sg * 8 + a;
            float* dst = g_D + (size_t)s * N_NODES + j0 + jb;
            if (full) {
                *(float4*)dst       = make_float4(accf[a][0], accf[a][1], accf[a][2], accf[a][3]);
                *(float4*)(dst + 4) = make_float4(accf[a][4], accf[a][5], accf[a][6], accf[a][7]);
            } else {
                for (int c = 0; c < 8; ++c) if (jb + c < nvalid) dst[c] = accf[a][c];
            }
        }
#pragma unroll
        for (int c = 0; c < 8; ++c) {
            if (full || jb + c < nvalid) {
                float* dst = &g_DT[(size_t)(j0 + jb + c) * NS + sg * 8];
                *(float4*)dst       = make_float4(accf[0][c], accf[1][c], accf[2][c], accf[3][c]);
                *(float4*)(dst + 4) = make_float4(accf[4][c], accf[5][c], accf[6][c], accf[7][c]);
            }
        }
    }
}

// ---------------- K3: per (sample,slice) top-CANDN via PQ + top-k selection network ----------------
__global__ __launch_bounds__(256) void k_cand() {
    __shared__ u64 keys[2048];
    int slice = blockIdx.x, i = blockIdx.y, tid = threadIdx.x;
    float xn = __ldg(&g_G[i * NS + i]);
    const float* Drow = g_D + (size_t)i * N_NODES;
    int base = slice * SLICEN, jend = base + SLICEN;

    u64 K[TK];
#pragma unroll
    for (int m = 0; m < TK; ++m) K[m] = ~0ull;

    for (int j = base + tid; j < jend; j += 1024) {
        float d[4]; int jj[4]; bool ok[4];
#pragma unroll
        for (int q = 0; q < 4; ++q) {
            jj[q] = j + q * 256;
            ok[q] = jj[q] < jend;
            int js = ok[q] ? jj[q] : base;
            d[q] = xn - 2.f * __ldg(&Drow[js]) + __ldg(&g_vn[js]);
        }
#pragma unroll
        for (int q = 0; q < 4; ++q) {
            if (ok[q]) {
                u64 key = ((u64)__float_as_uint(d[q]) << 32) | (unsigned)jj[q];
                if (key < K[TK - 1]) {
                    K[TK - 1] = key;
#pragma unroll
                    for (int m = TK - 1; m > 0; --m) {
                        u64 a = u64min(K[m - 1], K[m]);
                        u64 b = u64max(K[m - 1], K[m]);
                        K[m - 1] = a; K[m] = b;
                    }
                }
            }
        }
    }
    // store per-thread run; odd threads reversed so 16-blocks are bitonic
#pragma unroll
    for (int m = 0; m < TK; ++m)
        keys[tid * TK + m] = (tid & 1) ? K[TK - 1 - m] : K[m];
    __syncthreads();

    // bitonic continue from k=16 up to 256 (final level forced ascending per 256-block)
    for (int k = 16; k <= 256; k <<= 1) {
        for (int j2 = k >> 1; j2 > 0; j2 >>= 1) {
            for (int t = tid; t < 1024; t += 256) {
                int a = ((t & ~(j2 - 1)) << 1) | (t & (j2 - 1));
                bool up = (k == 256) ? true : ((a & k) == 0);
                u64 x = keys[a], y = keys[a + j2];
                if ((x > y) == up) { keys[a] = y; keys[a + j2] = x; }
            }
            __syncthreads();
        }
    }
    // top-k merge: 8 sorted 256-blocks -> 256 via halver + clean, 3 levels
#pragma unroll
    for (int L = 0; L < 3; ++L) {
        int npairs = 4 >> L;
        int pairstride = 512 << L;
        int nops = npairs << 8;
        for (int t = tid; t < nops; t += 256) {
            int p = t >> 8, ii = t & 255;
            int a = p * pairstride + ii;
            int b = p * pairstride + (pairstride >> 1) + 255 - ii;
            u64 x = keys[a], y = keys[b];
            if (y < x) { keys[a] = y; keys[b] = x; }
        }
        __syncthreads();
        for (int j2 = 128; j2 > 0; j2 >>= 1) {
            int cops = npairs << 7;
            for (int t = tid; t < cops; t += 256) {
                int p = t >> 7, q = t & 127;
                int idx = ((q & ~(j2 - 1)) << 1) | (q & (j2 - 1));
                int a = p * pairstride + idx;
                u64 x = keys[a], y = keys[a + j2];
                if (y < x) { keys[a] = y; keys[a + j2] = x; }
            }
            __syncthreads();
        }
    }
    if (tid < CANDN)
        g_scand[((size_t)i * NSLICE + slice) * CANDN + tid] = keys[tid];
}

// ---------------- K3b: merge 8 sorted lists -> global top-160 ----------------
__global__ __launch_bounds__(512) void k_merge() {
    __shared__ u64 keys[2048];
    int i = blockIdx.x, tid = threadIdx.x;
    for (int t = tid; t < 2048; t += 512) {
        int list = t >> 8, pos = t & 255;
        keys[t] = (pos < CANDN) ? __ldg(&g_scand[((size_t)i * NSLICE + list) * CANDN + pos]) : ~0ull;
    }
    __syncthreads();
#pragma unroll
    for (int L = 0; L < 3; ++L) {
        int npairs = 4 >> L;
        int pairstride = 512 << L;
        int nops = npairs << 8;
        for (int t = tid; t < nops; t += 512) {
            int p = t >> 8, ii = t & 255;
            int a = p * pairstride + ii;
            int b = p * pairstride + (pairstride >> 1) + 255 - ii;
            u64 x = keys[a], y = keys[b];
            if (y < x) { keys[a] = y; keys[b] = x; }
        }
        __syncthreads();
        for (int j2 = 128; j2 > 0; j2 >>= 1) {
            int cops = npairs << 7;
            for (int t = tid; t < cops; t += 512) {
                int p = t >> 7, q = t & 127;
                int idx = ((q & ~(j2 - 1)) << 1) | (q & (j2 - 1));
                int a = p * pairstride + idx;
                u64 x = keys[a], y = keys[a + j2];
                if (y < x) { keys[a] = y; keys[a + j2] = x; }
            }
            __syncthreads();
        }
    }
    if (tid < CANDN) g_cand[i * CANDN + tid] = keys[tid];
}

// ---------------- K4: sequential BMU loop, single warp, sorted-list early exit ----------------
#define SEQ_SMEM (NS * CANDN * 8 + NS * NS * 4 + 64 * 129 * 4 + MODCAP * 4 + MODCAP * 4 + HSHN * 4 + BMW * 4 + 64)

__global__ __launch_bounds__(256) void k_seq(const int* __restrict__ itp, float* __restrict__ out) {
    extern __shared__ char smraw[];
    u64*      scand = (u64*)smraw;                  // NS*CANDN
    float*    sG    = (float*)(scand + NS * CANDN); // NS*NS
    float*    mdt   = sG + NS * NS;                 // 64*129 : mdt[t][m]
    float*    mvn   = mdt + 64 * 129;               // MODCAP
    int*      midx  = (int*)(mvn + MODCAP);         // MODCAP
    int*      hsh   = midx + MODCAP;                // HSHN
    unsigned* bm    = (unsigned*)(hsh + HSHN);      // BMW

    int tid = threadIdx.x;
    for (int t = tid; t < NS * CANDN; t += 256) scand[t] = __ldg(&g_cand[t]);
    for (int t = tid; t < NS * NS; t += 256) sG[t] = __ldg(&g_G[t]);
    for (int t = tid; t < BMW; t += 256) bm[t] = 0;
    for (int t = tid; t < HSHN; t += 256) hsh[t] = 0;
    __syncthreads();
    if (tid >= 32) return;   // single warp

    int lane = tid;
    int it = itp ? __ldg(itp) : 0;
    float eb = 1.0f / (float)(it + 2);
    float en = 1.0f / (float)((it + 1) * 100);
    float ebo = 1.f - eb, eno = 1.f - en;

    // prefetch top-4 candidate DT rows + vnorms for sample 0
    float pf0a, pf1a, pf2a, pf3a, pf0b, pf1b, pf2b, pf3b, pfvn = 0.f;
    {
        unsigned i0 = (unsigned)scand[0], i1 = (unsigned)scand[1];
        unsigned i2 = (unsigned)scand[2], i3 = (unsigned)scand[3];
        pf0a = __ldg(&g_DT[(size_t)i0 * NS + lane]); pf0b = __ldg(&g_DT[(size_t)i0 * NS + 32 + lane]);
        pf1a = __ldg(&g_DT[(size_t)i1 * NS + lane]); pf1b = __ldg(&g_DT[(size_t)i1 * NS + 32 + lane]);
        pf2a = __ldg(&g_DT[(size_t)i2 * NS + lane]); pf2b = __ldg(&g_DT[(size_t)i2 * NS + 32 + lane]);
        pf3a = __ldg(&g_DT[(size_t)i3 * NS + lane]); pf3b = __ldg(&g_DT[(size_t)i3 * NS + 32 + lane]);
        if (lane < 4) pfvn = __ldg(&g_vn[(unsigned)scand[lane]]);
    }
    int nmod = 0;

    for (int i = 0; i < NS; ++i) {
        float xn = sG[i * NS + i];

        // ---- candidate side: first 2 unmodified keys of the sorted list ----
        u64 k1c = ~0ull, k2c = ~0ull;
        int r1 = 0, r2 = 0, found = 0;
        for (int b = 0; b < 5 && found < 2; ++b) {
            u64 key = scand[i * CANDN + b * 32 + lane];
            unsigned idx = (unsigned)key;
            bool um = !((bm[idx >> 5] >> (idx & 31)) & 1u);
            unsigned msk = __ballot_sync(0xffffffffu, um);
            while (msk && found < 2) {
                int l = __ffs(msk) - 1; msk &= msk - 1;
                u64 kk = __shfl_sync(0xffffffffu, key, l);
                if (!found) { k1c = kk; r1 = b * 32 + l; }
                else        { k2c = kk; r2 = b * 32 + l; }
                ++found;
            }
        }

        // ---- mod-table side: exact top-2 over current modified nodes ----
        u64 m1 = ~0ull, m2 = ~0ull;
        int qmax = (nmod + 31) >> 5;
        for (int q = 0; q < qmax; ++q) {
            int m = q * 32 + lane;
            if (m < nmod) {
                float d2 = xn - 2.f * mdt[i * 129 + m] + mvn[m];
                u64 key = ((u64)__float_as_uint(d2) << 32) | (unsigned)midx[m];
                if (key < m1) { m2 = m1; m1 = key; } else if (key < m2) m2 = key;
            }
        }
#pragma unroll
        for (int off = 16; off; off >>= 1) {
            u64 b1 = __shfl_xor_sync(0xffffffffu, m1, off);
            u64 b2 = __shfl_xor_sync(0xffffffffu, m2, off);
            u64 mm1 = u64min(m1, b1);
            u64 mm2 = u64min(u64max(m1, b1), u64min(m2, b2));
            m1 = mm1; m2 = mm2;
        }

        // ---- merge two sorted pairs ----
        u64 k1 = u64min(k1c, m1);
        u64 k2 = u64min(u64max(k1c, m1), u64min(k2c, m2));
        unsigned nb = (unsigned)k1, nsd = (unsigned)k2;
        bool newb = (k1 == k1c);
        bool news = (k2 == k2c) || (k2 == k1c);
        int rank_b = r1;
        int rank_s = (k2 == k1c) ? r1 : r2;

        if (lane == 0) {
            out[2 * i]     = sqrtf(__uint_as_float((unsigned)(k1 >> 32)) + 1e-12f);
            out[2 * i + 1] = sqrtf(__uint_as_float((unsigned)(k2 >> 32)) + 1e-12f);
        }

        // ---- slot resolution ----
        int slot_b = nmod, slot_s = nmod + (newb ? 1 : 0);
        if (!newb) {
            int s = 0;
            if (lane == 0) {
                unsigned h = (nb * 2654435761u) >> 21;
                while (true) {
                    int e = hsh[h];
                    if (e && midx[e - 1] == (int)nb) { s = e - 1; break; }
                    h = (h + 1) & (HSHN - 1);
                }
            }
            slot_b = __shfl_sync(0xffffffffu, s, 0);
        }
        if (!news) {
            int s = 0;
            if (lane == 0) {
                unsigned h = (nsd * 2654435761u) >> 21;
                while (true) {
                    int e = hsh[h];
                    if (e && midx[e - 1] == (int)nsd) { s = e - 1; break; }
                    h = (h + 1) & (HSHN - 1);
                }
            }
            slot_s = __shfl_sync(0xffffffffu, s, 0);
        }

        // ---- gather old rows ----
        float ob0, ob1, os0, os1, vnb, vns;
        if (newb) {
            if (rank_b < 4) {
                ob0 = rank_b == 0 ? pf0a : rank_b == 1 ? pf1a : rank_b == 2 ? pf2a : pf3a;
                ob1 = rank_b == 0 ? pf0b : rank_b == 1 ? pf1b : rank_b == 2 ? pf2b : pf3b;
                vnb = __shfl_sync(0xffffffffu, pfvn, rank_b);
            } else {
                ob0 = __ldg(&g_DT[(size_t)nb * NS + lane]);
                ob1 = __ldg(&g_DT[(size_t)nb * NS + 32 + lane]);
                vnb = __ldg(&g_vn[nb]);
            }
        } else {
            ob0 = mdt[lane * 129 + slot_b];
            ob1 = mdt[(32 + lane) * 129 + slot_b];
            vnb = mvn[slot_b];
        }
        if (news) {
            if (rank_s < 4) {
                os0 = rank_s == 0 ? pf0a : rank_s == 1 ? pf1a : rank_s == 2 ? pf2a : pf3a;
                os1 = rank_s == 0 ? pf0b : rank_s == 1 ? pf1b : rank_s == 2 ? pf2b : pf3b;
                vns = __shfl_sync(0xffffffffu, pfvn, rank_s);
            } else {
                os0 = __ldg(&g_DT[(size_t)nsd * NS + lane]);
                os1 = __ldg(&g_DT[(size_t)nsd * NS + 32 + lane]);
                vns = __ldg(&g_vn[nsd]);
            }
        } else {
            os0 = mdt[lane * 129 + slot_s];
            os1 = mdt[(32 + lane) * 129 + slot_s];
            vns = mvn[slot_s];
        }
        float obi = __shfl_sync(0xffffffffu, (i < 32) ? ob0 : ob1, i & 31);
        float osi = __shfl_sync(0xffffffffu, (i < 32) ? os0 : os1, i & 31);

        __syncwarp();   // reads of mdt/mvn/bm/hsh complete before mutation

        float gr0 = sG[i * NS + lane], gr1 = sG[i * NS + 32 + lane];
        mdt[lane * 129 + slot_b]        = ebo * ob0 + eb * gr0;
        mdt[(32 + lane) * 129 + slot_b] = ebo * ob1 + eb * gr1;
        mdt[lane * 129 + slot_s]        = eno * os0 + en * gr0;
        mdt[(32 + lane) * 129 + slot_s] = eno * os1 + en * gr1;
        if (lane == 0) {
            mvn[slot_b] = ebo * ebo * vnb + 2.f * eb * ebo * obi + eb * eb * xn;
            mvn[slot_s] = eno * eno * vns + 2.f * en * eno * osi + en * en * xn;
            if (newb) {
                midx[slot_b] = (int)nb; bm[nb >> 5] |= 1u << (nb & 31);
                unsigned h = (nb * 2654435761u) >> 21;
                while (hsh[h]) h = (h + 1) & (HSHN - 1);
                hsh[h] = slot_b + 1;
            }
            if (news) {
                midx[slot_s] = (int)nsd; bm[nsd >> 5] |= 1u << (nsd & 31);
                unsigned h = (nsd * 2654435761u) >> 21;
                while (hsh[h]) h = (h + 1) & (HSHN - 1);
                hsh[h] = slot_s + 1;
            }
        }
        nmod += (newb ? 1 : 0) + (news ? 1 : 0);

        // prefetch next sample's top-4 candidate rows + vnorms
        if (i + 1 < NS) {
            unsigned i0 = (unsigned)scand[(i + 1) * CANDN + 0];
            unsigned i1 = (unsigned)scand[(i + 1) * CANDN + 1];
            unsigned i2 = (unsigned)scand[(i + 1) * CANDN + 2];
            unsigned i3 = (unsigned)scand[(i + 1) * CANDN + 3];
            pf0a = __ldg(&g_DT[(size_t)i0 * NS + lane]); pf0b = __ldg(&g_DT[(size_t)i0 * NS + 32 + lane]);
            pf1a = __ldg(&g_DT[(size_t)i1 * NS + lane]); pf1b = __ldg(&g_DT[(size_t)i1 * NS + 32 + lane]);
            pf2a = __ldg(&g_DT[(size_t)i2 * NS + lane]); pf2b = __ldg(&g_DT[(size_t)i2 * NS + 32 + lane]);
            pf3a = __ldg(&g_DT[(size_t)i3 * NS + lane]); pf3b = __ldg(&g_DT[(size_t)i3 * NS + 32 + lane]);
            if (lane < 4) pfvn = __ldg(&g_vn[(unsigned)scand[(i + 1) * CANDN + lane]]);
        }
        __syncwarp();   // mutations visible before next selection
    }
}

extern "C" void kernel_launch(void* const* d_in, const int* in_sizes, int n_in,
                              void* d_out, int out_size) {
    const float* X = (const float*)d_in[0];     // data [64,256]
    const float* V = (const float*)d_in[1];     // V [100000,256]
    const int* itp = (n_in > 3) ? (const int*)d_in[3] : nullptr;
    float* out = (float*)d_out;                 // [64,2]

    cudaFuncSetAttribute(k_seq, cudaFuncAttributeMaxDynamicSharedMemorySize, SEQ_SMEM);

    k_gram<<<NS, 256>>>(X);
    k_gemm<<<(N_NODES + NPC - 1) / NPC, 256>>>(X, V);
    k_cand<<<dim3(NSLICE, NS), 256>>>();
    k_merge<<<NS, 512>>>();
    k_seq<<<1, 256, SEQ_SMEM>>>(itp, out);
}